// round 8
// baseline (speedup 1.0000x reference)
#include <cuda_runtime.h>
#include <cuda_bf16.h>

#define N_NODES 50000
#define N_EDGES 800000
#define D 64
#define N_GRAPHS 1024
#define N_LAYERS 4
#define BN_EPS 1e-5f

#define SCAN_BLK 512
#define SCAN_NBLK ((N_NODES + SCAN_BLK - 1) / SCAN_BLK)   // 98
#define GATHER_GRID 1184                                  // 148*8 blocks
#define GEMM_NT ((N_NODES + 63) / 64)                     // 782 row tiles
#define GEMM_GRID 296                                     // 148 SM * 2 blocks
#define HPAD 68                                           // 16B-aligned rows (68%4==0)

// ---------------- scratch (device globals; no allocations allowed) ----------
__device__ __align__(16) float g_u[N_NODES * D];      // (h@W)*dinv[row]
__device__ __align__(16) float g_y[N_NODES * D];      // pre-BN activations
__device__ __align__(16) float g_dinv[N_NODES];       // rsqrt(deg)
__device__ __align__(16) float g_pooled[N_GRAPHS * D];
__device__ __align__(16) float g_stats[2 * D];        // [sum, sumsq]
__device__ __align__(16) float g_scale[D];
__device__ __align__(16) float g_shift[D];
__device__ int   g_count[N_NODES];                    // in-degree histogram
__device__ int   g_rowtmp[N_NODES];                   // local exclusive scan
__device__ int   g_rowstart[N_NODES + 1];             // CSR row offsets
__device__ int   g_cursor[N_NODES];                   // fill cursors
__device__ int   g_csrc[N_EDGES];                     // CSR src lists (by dst)
__device__ int   g_bsum[SCAN_NBLK + 2];               // scan block sums
__device__ unsigned int g_cnt;                         // last-block ticket

// vectorized global reduction (fp32 add, no return) — sm_90+
__device__ __forceinline__ void red_add_v4(float* addr, float4 v) {
    asm volatile("red.global.add.v4.f32 [%0], {%1,%2,%3,%4};"
                 :: "l"(addr), "f"(v.x), "f"(v.y), "f"(v.z), "f"(v.w)
                 : "memory");
}

// ---------------- setup kernels ---------------------------------------------

__global__ void k_init() {
    int i = blockIdx.x * blockDim.x + threadIdx.x;
    if (i < N_NODES) g_count[i] = 0;
    if (i < N_GRAPHS * D) g_pooled[i] = 0.0f;
    if (i == 0) g_cnt = 0u;
}

__global__ void k_count(const int* __restrict__ ei) {
    int e = blockIdx.x * blockDim.x + threadIdx.x;
    if (e < N_EDGES) atomicAdd(&g_count[ei[N_EDGES + e]], 1);
}

// block-local scan + block sums
__global__ void k_scan1() {
    __shared__ int sm[SCAN_BLK];
    int i = blockIdx.x * SCAN_BLK + threadIdx.x;
    int v = (i < N_NODES) ? g_count[i] : 0;
    sm[threadIdx.x] = v;
    __syncthreads();
    for (int off = 1; off < SCAN_BLK; off <<= 1) {
        int t = (threadIdx.x >= off) ? sm[threadIdx.x - off] : 0;
        __syncthreads();
        sm[threadIdx.x] += t;
        __syncthreads();
    }
    if (i < N_NODES) g_rowtmp[i] = sm[threadIdx.x] - v;  // exclusive
    if (threadIdx.x == SCAN_BLK - 1) g_bsum[blockIdx.x] = sm[SCAN_BLK - 1];
}

// parallel exclusive scan of the 98 block sums (single block, shared mem)
__global__ void k_scan2() {
    __shared__ int sm[128];
    int t = threadIdx.x;
    int v = (t < SCAN_NBLK) ? g_bsum[t] : 0;
    sm[t] = v;
    __syncthreads();
    #pragma unroll
    for (int off = 1; off < 128; off <<= 1) {
        int u = (t >= off) ? sm[t - off] : 0;
        __syncthreads();
        sm[t] += u;
        __syncthreads();
    }
    if (t < SCAN_NBLK) g_bsum[t] = sm[t] - v;  // exclusive
}

// finalize rowstart/cursor + dinv
__global__ void k_scan3() {
    int i = blockIdx.x * blockDim.x + threadIdx.x;
    if (i < N_NODES) {
        int rs = g_rowtmp[i] + g_bsum[i >> 9];   // 512 = 2^9
        g_rowstart[i] = rs;
        g_cursor[i]   = rs;
        g_dinv[i] = rsqrtf((float)g_count[i] + 1.0f);
    }
    if (i == 0) g_rowstart[N_NODES] = N_EDGES;
}

__global__ void k_fill(const int* __restrict__ ei) {
    int e = blockIdx.x * blockDim.x + threadIdx.x;
    if (e < N_EDGES) {
        int s = ei[e];
        int d = ei[N_EDGES + e];
        int pos = atomicAdd(&g_cursor[d], 1);
        g_csrc[pos] = s;
    }
}

// ---------------- per-layer kernels ------------------------------------------

// Persistent GEMM: u[r][c] = (sum_k h[r][k]*W[k][c]) * dinv[r].
// hin == nullptr => h = relu(g_y * g_scale + g_shift) (fused BN+ReLU).
// W resident in smem for the whole kernel. Single h buffer; tile t+1's global
// loads land in registers while tile t computes, then sync/STS/sync.
// Smem: 16384 (W) + 64*68*4 (h) + 512 = 34.3 KB -> fits static, 2 blocks/SM.
__global__ void __launch_bounds__(256, 2) k_gemm(const float* __restrict__ hin_arg,
                                                 const float* __restrict__ W) {
    __shared__ float Wsh[64 * 64];
    __shared__ float hsT[64 * HPAD];
    __shared__ float ssc[64], ssh[64];

    const int tid = threadIdx.x;
    const int tx = tid & 15;            // c0 = tx*4
    const int ty = tid >> 4;            // r0 = ty*4
    const int kcol = tid & 63;          // load-phase: fixed k-column per thread
    const int rb   = tid >> 6;          // load-phase: row sub-offset 0..3

    if (blockIdx.x == 0 && tid < 2 * D) g_stats[tid] = 0.0f;  // pre-layer zero
    if (tid < 64) { ssc[tid] = g_scale[tid]; ssh[tid] = g_shift[tid]; }

    for (int i = tid; i < 64 * 64; i += 256) Wsh[i] = W[i];

    const bool bn = (hin_arg == nullptr);
    const float* src = bn ? (const float*)g_y : hin_arg;

    // prefetch tile0 into registers
    float tmp[16];
    int tile = blockIdx.x;
    #pragma unroll
    for (int j = 0; j < 16; j++) {
        int r = tile * 64 + rb + j * 4;
        tmp[j] = (r < N_NODES) ? __ldg(&src[r * D + kcol]) : 0.0f;
    }
    __syncthreads();   // Wsh, ssc, ssh visible

    float sck = 1.0f, shk = 0.0f;
    if (bn) { sck = ssc[kcol]; shk = ssh[kcol]; }

    const int r0 = ty * 4, c0 = tx * 4;

    for (; tile < GEMM_NT; tile += GEMM_GRID) {
        // store prefetched tile (BN+ReLU applied for layers >= 1)
        #pragma unroll
        for (int j = 0; j < 16; j++) {
            float v = tmp[j];
            if (bn) v = fmaxf(v * sck + shk, 0.0f);
            hsT[kcol * HPAD + rb + j * 4] = v;
        }
        __syncthreads();

        // kick off next tile's global loads (overlap with FFMA loop)
        const int next = tile + GEMM_GRID;
        if (next < GEMM_NT) {
            #pragma unroll
            for (int j = 0; j < 16; j++) {
                int r = next * 64 + rb + j * 4;
                tmp[j] = (r < N_NODES) ? __ldg(&src[r * D + kcol]) : 0.0f;
            }
        }

        float acc[4][4];
        #pragma unroll
        for (int a = 0; a < 4; a++)
            #pragma unroll
            for (int b = 0; b < 4; b++) acc[a][b] = 0.0f;

        float4 hv = *(const float4*)&hsT[r0];
        float4 wv = *(const float4*)&Wsh[c0];
        #pragma unroll
        for (int k = 0; k < 64; k++) {
            const int kn = (k + 1) & 63;
            float4 hn = *(const float4*)&hsT[kn * HPAD + r0];
            float4 wn = *(const float4*)&Wsh[kn * 64 + c0];
            acc[0][0] += hv.x * wv.x; acc[0][1] += hv.x * wv.y; acc[0][2] += hv.x * wv.z; acc[0][3] += hv.x * wv.w;
            acc[1][0] += hv.y * wv.x; acc[1][1] += hv.y * wv.y; acc[1][2] += hv.y * wv.z; acc[1][3] += hv.y * wv.w;
            acc[2][0] += hv.z * wv.x; acc[2][1] += hv.z * wv.y; acc[2][2] += hv.z * wv.z; acc[2][3] += hv.z * wv.w;
            acc[3][0] += hv.w * wv.x; acc[3][1] += hv.w * wv.y; acc[3][2] += hv.w * wv.z; acc[3][3] += hv.w * wv.w;
            hv = hn; wv = wn;
        }

        #pragma unroll
        for (int a = 0; a < 4; a++) {
            int r = tile * 64 + r0 + a;
            if (r < N_NODES) {
                float d = g_dinv[r];
                *(float4*)&g_u[r * D + c0] =
                    make_float4(acc[a][0] * d, acc[a][1] * d, acc[a][2] * d, acc[a][3] * d);
            }
        }
        __syncthreads();   // all reads of hsT done before next store
    }
}

// CSR gather + y + BN stats + ticket finalize.  One warp per node (grid-stride).
// Half-warps process alternating edges; lanes cover 64 cols as 16 x float4.
__global__ void __launch_bounds__(256) k_gather(const float* __restrict__ b,
                                                const float* __restrict__ gamma,
                                                const float* __restrict__ beta) {
    __shared__ float sm1[8 * 64];
    __shared__ float sm2[8 * 64];
    __shared__ bool isLast;

    const int tid = threadIdx.x;
    const int w = tid >> 5;
    const int lane = tid & 31;
    const int half = lane >> 4;
    const int cl = (lane & 15) << 2;

    float s1x = 0.f, s1y = 0.f, s1z = 0.f, s1w = 0.f;
    float s2x = 0.f, s2y = 0.f, s2z = 0.f, s2w = 0.f;
    const float4 bv = *(const float4*)&b[cl];

    for (int n = blockIdx.x * 8 + w; n < N_NODES; n += GATHER_GRID * 8) {
        const int beg = g_rowstart[n];
        const int end = g_rowstart[n + 1];
        float4 acc = make_float4(0.f, 0.f, 0.f, 0.f);
        for (int j = beg + half; j < end; j += 2) {
            int s = __ldg(&g_csrc[j]);
            float4 v = *(const float4*)&g_u[s * D + cl];
            acc.x += v.x; acc.y += v.y; acc.z += v.z; acc.w += v.w;
        }
        acc.x += __shfl_xor_sync(0xffffffffu, acc.x, 16);
        acc.y += __shfl_xor_sync(0xffffffffu, acc.y, 16);
        acc.z += __shfl_xor_sync(0xffffffffu, acc.z, 16);
        acc.w += __shfl_xor_sync(0xffffffffu, acc.w, 16);
        if (half == 0) {
            float4 us = *(const float4*)&g_u[n * D + cl];
            float dv = g_dinv[n];
            float4 y;
            y.x = dv * (acc.x + us.x) + bv.x;
            y.y = dv * (acc.y + us.y) + bv.y;
            y.z = dv * (acc.z + us.z) + bv.z;
            y.w = dv * (acc.w + us.w) + bv.w;
            *(float4*)&g_y[n * D + cl] = y;
            s1x += y.x; s1y += y.y; s1z += y.z; s1w += y.w;
            s2x += y.x * y.x; s2y += y.y * y.y; s2z += y.z * y.z; s2w += y.w * y.w;
        }
    }

    if (half == 0) {
        sm1[w * 64 + cl + 0] = s1x; sm1[w * 64 + cl + 1] = s1y;
        sm1[w * 64 + cl + 2] = s1z; sm1[w * 64 + cl + 3] = s1w;
        sm2[w * 64 + cl + 0] = s2x; sm2[w * 64 + cl + 1] = s2y;
        sm2[w * 64 + cl + 2] = s2z; sm2[w * 64 + cl + 3] = s2w;
    }
    __syncthreads();
    if (tid < 64) {
        float t1 = 0.f, t2 = 0.f;
        #pragma unroll
        for (int ww = 0; ww < 8; ww++) { t1 += sm1[ww * 64 + tid]; t2 += sm2[ww * 64 + tid]; }
        atomicAdd(&g_stats[tid], t1);
        atomicAdd(&g_stats[D + tid], t2);
    }
    __threadfence();
    if (tid == 0) isLast = (atomicAdd(&g_cnt, 1u) == (unsigned)(gridDim.x - 1));
    __syncthreads();
    if (isLast) {
        if (tid < 64) {
            float mean = g_stats[tid] * (1.0f / N_NODES);
            float var  = g_stats[D + tid] * (1.0f / N_NODES) - mean * mean;
            float sc = gamma[tid] * rsqrtf(var + BN_EPS);
            g_scale[tid] = sc;
            g_shift[tid] = beta[tid] - mean * sc;
        }
        if (tid == 0) g_cnt = 0u;   // rearm
    }
}

// final layer: h = relu(y*scale+shift); pooled[batch[n]] += h  (fused)
__global__ void k_poolfused(const int* __restrict__ batch) {
    long long idx = (long long)blockIdx.x * blockDim.x + threadIdx.x;
    if (idx >= (long long)N_NODES * 16) return;
    int n = (int)(idx >> 4);
    int c = (int)(idx & 15) << 2;
    int g = __ldg(&batch[n]);
    float4 y  = *(const float4*)&g_y[n * D + c];
    float4 sc = *(const float4*)&g_scale[c];
    float4 sh = *(const float4*)&g_shift[c];
    float4 h;
    h.x = fmaxf(y.x * sc.x + sh.x, 0.0f);
    h.y = fmaxf(y.y * sc.y + sh.y, 0.0f);
    h.z = fmaxf(y.z * sc.z + sh.z, 0.0f);
    h.w = fmaxf(y.w * sc.w + sh.w, 0.0f);
    red_add_v4(&g_pooled[g * D + c], h);
}

// tiny MLP head: one block per graph, 64 threads
__global__ void k_mlp(const float* __restrict__ w1, const float* __restrict__ b1,
                      const float* __restrict__ w2, const float* __restrict__ b2,
                      const float* __restrict__ w3, const float* __restrict__ b3,
                      float* __restrict__ out) {
    __shared__ float pr[64], z1[64], z2[64], red[64];
    const int g = blockIdx.x;
    const int c = threadIdx.x;
    pr[c] = g_pooled[g * D + c];
    __syncthreads();
    float a = b1[c];
    #pragma unroll 8
    for (int k = 0; k < 64; k++) a += pr[k] * w1[k * D + c];
    z1[c] = fmaxf(a, 0.0f);
    __syncthreads();
    a = b2[c];
    #pragma unroll 8
    for (int k = 0; k < 64; k++) a += z1[k] * w2[k * D + c];
    z2[c] = fmaxf(a, 0.0f);
    __syncthreads();
    red[c] = z2[c] * w3[c];
    __syncthreads();
    if (c == 0) {
        float s = b3[0];
        #pragma unroll
        for (int k = 0; k < 64; k++) s += red[k];
        out[g] = s;
    }
}

// ---------------- launch -----------------------------------------------------
extern "C" void kernel_launch(void* const* d_in, const int* in_sizes, int n_in,
                              void* d_out, int out_size) {
    const float* x     = (const float*)d_in[0];
    const int*   ei    = (const int*)d_in[1];
    const int*   batch = (const int*)d_in[2];
    const float* Ws    = (const float*)d_in[3];
    const float* bs    = (const float*)d_in[4];
    const float* gamma = (const float*)d_in[5];
    const float* beta  = (const float*)d_in[6];
    const float* w1    = (const float*)d_in[7];
    const float* b1    = (const float*)d_in[8];
    const float* w2    = (const float*)d_in[9];
    const float* b2    = (const float*)d_in[10];
    const float* w3    = (const float*)d_in[11];
    const float* b3    = (const float*)d_in[12];
    float* out = (float*)d_out;

    // CSR build (once per launch)
    k_init<<<(N_GRAPHS * D + 255) / 256, 256>>>();
    k_count<<<(N_EDGES + 255) / 256, 256>>>(ei);
    k_scan1<<<SCAN_NBLK, SCAN_BLK>>>();
    k_scan2<<<1, 128>>>();
    k_scan3<<<(N_NODES + 255) / 256, 256>>>();
    k_fill<<<(N_EDGES + 255) / 256, 256>>>(ei);

    for (int l = 0; l < N_LAYERS; l++) {
        const float* hin = (l == 0) ? x : nullptr;  // nullptr => fused BN+ReLU from g_y
        k_gemm<<<GEMM_GRID, 256>>>(hin, Ws + l * D * D);
        k_gather<<<GATHER_GRID, 256>>>(bs + l * D, gamma + l * D, beta + l * D);
    }

    k_poolfused<<<(N_NODES * 16) / 256, 256>>>(batch);
    k_mlp<<<N_GRAPHS, 64>>>(w1, b1, w2, b2, w3, b3, out);
}

// round 10
// speedup vs baseline: 1.0223x; 1.0223x over previous
#include <cuda_runtime.h>
#include <cuda_bf16.h>
#include <cstdint>

#define N_NODES 50000
#define N_EDGES 800000
#define D 64
#define N_GRAPHS 1024
#define N_LAYERS 4
#define BN_EPS 1e-5f

#define SCAN_BLK 512
#define SCAN_NBLK ((N_NODES + SCAN_BLK - 1) / SCAN_BLK)   // 98
#define GATHER_GRID 1184                                  // 148*8 blocks
#define GEMM_NT ((N_NODES + 63) / 64)                     // 782 row tiles
#define HPAD 68                                           // smem row pad (16B-aligned)

// ---------------- scratch (device globals; no allocations allowed) ----------
__device__ __align__(16) float g_u[N_NODES * D];      // (h@W)*dinv[row]
__device__ __align__(16) float g_y[N_NODES * D];      // pre-BN activations
__device__ __align__(16) float g_dinv[N_NODES];       // rsqrt(deg)
__device__ __align__(16) float g_pooled[N_GRAPHS * D];
__device__ __align__(16) float g_stats[2 * D];        // [sum, sumsq]
__device__ __align__(16) float g_scale[D];
__device__ __align__(16) float g_shift[D];
__device__ int   g_count[N_NODES];                    // in-degree histogram
__device__ int   g_rowtmp[N_NODES];                   // local exclusive scan
__device__ int   g_rowstart[N_NODES + 1];             // CSR row offsets
__device__ int   g_cursor[N_NODES];                   // fill cursors
__device__ int   g_csrc[N_EDGES];                     // CSR src lists (by dst)
__device__ int   g_bsum[SCAN_NBLK + 2];               // scan block sums
__device__ unsigned int g_cnt;                         // last-block ticket

// vectorized global reduction (fp32 add, no return) — sm_90+
__device__ __forceinline__ void red_add_v4(float* addr, float4 v) {
    asm volatile("red.global.add.v4.f32 [%0], {%1,%2,%3,%4};"
                 :: "l"(addr), "f"(v.x), "f"(v.y), "f"(v.z), "f"(v.w)
                 : "memory");
}

// fp32 -> tf32 (round-to-nearest); result reinterpretable as fp32 with low bits zeroed
__device__ __forceinline__ uint32_t f2tf32(float x) {
    uint32_t r;
    asm("cvt.rna.tf32.f32 %0, %1;" : "=r"(r) : "f"(x));
    return r;
}

__device__ __forceinline__ void mma_tf32(float& d0, float& d1, float& d2, float& d3,
                                         uint32_t a0, uint32_t a1, uint32_t a2, uint32_t a3,
                                         uint32_t b0, uint32_t b1) {
    asm volatile(
        "mma.sync.aligned.m16n8k8.row.col.f32.tf32.tf32.f32 "
        "{%0,%1,%2,%3}, {%4,%5,%6,%7}, {%8,%9}, {%0,%1,%2,%3};"
        : "+f"(d0), "+f"(d1), "+f"(d2), "+f"(d3)
        : "r"(a0), "r"(a1), "r"(a2), "r"(a3), "r"(b0), "r"(b1));
}

// ---------------- setup kernels ---------------------------------------------

__global__ void k_init() {
    int i = blockIdx.x * blockDim.x + threadIdx.x;
    if (i < N_NODES) g_count[i] = 0;
    if (i < N_GRAPHS * D) g_pooled[i] = 0.0f;
    if (i == 0) g_cnt = 0u;
}

__global__ void k_count(const int* __restrict__ ei) {
    int e = blockIdx.x * blockDim.x + threadIdx.x;
    if (e < N_EDGES) atomicAdd(&g_count[ei[N_EDGES + e]], 1);
}

__global__ void k_scan1() {
    __shared__ int sm[SCAN_BLK];
    int i = blockIdx.x * SCAN_BLK + threadIdx.x;
    int v = (i < N_NODES) ? g_count[i] : 0;
    sm[threadIdx.x] = v;
    __syncthreads();
    for (int off = 1; off < SCAN_BLK; off <<= 1) {
        int t = (threadIdx.x >= off) ? sm[threadIdx.x - off] : 0;
        __syncthreads();
        sm[threadIdx.x] += t;
        __syncthreads();
    }
    if (i < N_NODES) g_rowtmp[i] = sm[threadIdx.x] - v;  // exclusive
    if (threadIdx.x == SCAN_BLK - 1) g_bsum[blockIdx.x] = sm[SCAN_BLK - 1];
}

__global__ void k_scan2() {
    __shared__ int sm[128];
    int t = threadIdx.x;
    int v = (t < SCAN_NBLK) ? g_bsum[t] : 0;
    sm[t] = v;
    __syncthreads();
    #pragma unroll
    for (int off = 1; off < 128; off <<= 1) {
        int u = (t >= off) ? sm[t - off] : 0;
        __syncthreads();
        sm[t] += u;
        __syncthreads();
    }
    if (t < SCAN_NBLK) g_bsum[t] = sm[t] - v;  // exclusive
}

__global__ void k_scan3() {
    int i = blockIdx.x * blockDim.x + threadIdx.x;
    if (i < N_NODES) {
        int rs = g_rowtmp[i] + g_bsum[i >> 9];
        g_rowstart[i] = rs;
        g_cursor[i]   = rs;
        g_dinv[i] = rsqrtf((float)g_count[i] + 1.0f);
    }
    if (i == 0) g_rowstart[N_NODES] = N_EDGES;
}

__global__ void k_fill(const int* __restrict__ ei) {
    int e = blockIdx.x * blockDim.x + threadIdx.x;
    if (e < N_EDGES) {
        int s = ei[e];
        int d = ei[N_EDGES + e];
        int pos = atomicAdd(&g_cursor[d], 1);
        g_csrc[pos] = s;
    }
}

// ---------------- per-layer kernels ------------------------------------------

// Tensor-core GEMM via C^T = W^T x H^T with 3xTF32 splitting.
// u[r][c] = (sum_k h[r][k]*W[k][c]) * dinv[r];
// hin == nullptr => h = relu(g_y * g_scale + g_shift) (fused BN+ReLU).
// Per block: one 64-node tile. W^T fragments are register-stationary per warp
// (warp's c-strip = (w&3)*16); H tile staged in smem (reused buffer after W).
__global__ void __launch_bounds__(256, 2) k_gemm(const float* __restrict__ hin_arg,
                                                 const float* __restrict__ W) {
    __shared__ __align__(16) float hs[64 * HPAD];   // W staging first, then H tile
    __shared__ float ssc[64], ssh[64], sdinv[64];

    const int tid  = threadIdx.x;
    const int lane = tid & 31;
    const int w    = tid >> 5;
    const int grp  = lane >> 2;     // 0..7
    const int tg   = lane & 3;      // 0..3
    const int cs   = (w & 3) * 16;  // c-strip base
    const int ng   = w >> 2;        // node half: 0/1
    const int row0 = blockIdx.x * 64;

    if (blockIdx.x == 0 && tid < 2 * D) g_stats[tid] = 0.0f;  // pre-layer zero
    if (tid < 64) { ssc[tid] = g_scale[tid]; ssh[tid] = g_shift[tid]; }
    if (tid < 64) sdinv[tid] = (row0 + tid < N_NODES) ? g_dinv[row0 + tid] : 0.0f;

    // ---- Phase 1: stage W (row-major 64x64, stride 64) ----
    for (int i = tid; i < 64 * 64; i += 256) hs[i] = W[i];
    __syncthreads();

    // ---- Phase 2: pull stationary A = W^T fragments (hi + lo) ----
    // A = W^T (row-major, A[c][k] = W[k][c]), m16n8k8 A-frag:
    // a0(s)=W[8s+tg][cs+grp], a1=W[8s+tg][cs+grp+8], a2=W[8s+tg+4][cs+grp], a3=W[8s+tg+4][cs+grp+8]
    uint32_t ahi[8][4], alo[8][4];
    #pragma unroll
    for (int s = 0; s < 8; s++) {
        float v[4];
        v[0] = hs[(8 * s + tg) * 64 + cs + grp];
        v[1] = hs[(8 * s + tg) * 64 + cs + grp + 8];
        v[2] = hs[(8 * s + tg + 4) * 64 + cs + grp];
        v[3] = hs[(8 * s + tg + 4) * 64 + cs + grp + 8];
        #pragma unroll
        for (int j = 0; j < 4; j++) {
            uint32_t h = f2tf32(v[j]);
            ahi[s][j] = h;
            alo[s][j] = f2tf32(v[j] - __uint_as_float(h));
        }
    }
    __syncthreads();   // done reading W; hs can be reused

    // ---- Phase 3: stage H tile (64 rows x 64 k, stride HPAD), BN fused ----
    const bool bn = (hin_arg == nullptr);
    const float* src = bn ? (const float*)g_y : hin_arg;
    {
        const int rr = tid >> 4;          // 0..15
        const int kk = (tid & 15) << 2;   // 0,4,..,60
        float4 sc4, sh4;
        if (bn) { sc4 = *(const float4*)&ssc[kk]; sh4 = *(const float4*)&ssh[kk]; }
        #pragma unroll
        for (int j = 0; j < 4; j++) {
            int r = rr + j * 16;
            int gr = row0 + r;
            float4 v = make_float4(0.f, 0.f, 0.f, 0.f);
            if (gr < N_NODES) v = *(const float4*)&src[gr * D + kk];
            if (bn) {
                v.x = fmaxf(v.x * sc4.x + sh4.x, 0.0f);
                v.y = fmaxf(v.y * sc4.y + sh4.y, 0.0f);
                v.z = fmaxf(v.z * sc4.z + sh4.z, 0.0f);
                v.w = fmaxf(v.w * sc4.w + sh4.w, 0.0f);
            }
            *(float4*)&hs[r * HPAD + kk] = v;
        }
    }
    __syncthreads();

    // ---- Phase 4: compute. Warp covers c-strip [cs,cs+16), nodes [ng*32, ng*32+32) ----
    #pragma unroll
    for (int chunk = 0; chunk < 4; chunk++) {
        const int n0l = ng * 32 + chunk * 8;
        float d0 = 0.f, d1 = 0.f, d2 = 0.f, d3 = 0.f;
        #pragma unroll
        for (int s = 0; s < 8; s++) {
            // B = H^T col-major => B-frag from H rows: b0 = H[n0+grp][8s+tg], b1 = H[n0+grp][8s+tg+4]
            float bv0 = hs[(n0l + grp) * HPAD + 8 * s + tg];
            float bv1 = hs[(n0l + grp) * HPAD + 8 * s + tg + 4];
            uint32_t bh0 = f2tf32(bv0), bh1 = f2tf32(bv1);
            uint32_t bl0 = f2tf32(bv0 - __uint_as_float(bh0));
            uint32_t bl1 = f2tf32(bv1 - __uint_as_float(bh1));
            mma_tf32(d0, d1, d2, d3, ahi[s][0], ahi[s][1], ahi[s][2], ahi[s][3], bh0, bh1);
            mma_tf32(d0, d1, d2, d3, ahi[s][0], ahi[s][1], ahi[s][2], ahi[s][3], bl0, bl1);
            mma_tf32(d0, d1, d2, d3, alo[s][0], alo[s][1], alo[s][2], alo[s][3], bh0, bh1);
        }
        // C^T frag -> g_u: d0=C^T[grp][2tg], d1=[grp][2tg+1], d2=[grp+8][2tg], d3=[grp+8][2tg+1]
        const int nA = row0 + n0l + 2 * tg;
        const int nB = nA + 1;
        const float dvA = sdinv[n0l + 2 * tg];
        const float dvB = sdinv[n0l + 2 * tg + 1];
        const int cA = cs + grp, cB = cs + grp + 8;
        if (nA < N_NODES) { g_u[nA * D + cA] = d0 * dvA; g_u[nA * D + cB] = d2 * dvA; }
        if (nB < N_NODES) { g_u[nB * D + cA] = d1 * dvB; g_u[nB * D + cB] = d3 * dvB; }
    }
}

// CSR gather + y + BN stats + ticket finalize.  One warp per node (grid-stride).
__global__ void __launch_bounds__(256) k_gather(const float* __restrict__ b,
                                                const float* __restrict__ gamma,
                                                const float* __restrict__ beta) {
    __shared__ float sm1[8 * 64];
    __shared__ float sm2[8 * 64];
    __shared__ bool isLast;

    const int tid = threadIdx.x;
    const int w = tid >> 5;
    const int lane = tid & 31;
    const int half = lane >> 4;
    const int cl = (lane & 15) << 2;

    float s1x = 0.f, s1y = 0.f, s1z = 0.f, s1w = 0.f;
    float s2x = 0.f, s2y = 0.f, s2z = 0.f, s2w = 0.f;
    const float4 bv = *(const float4*)&b[cl];

    for (int n = blockIdx.x * 8 + w; n < N_NODES; n += GATHER_GRID * 8) {
        const int beg = g_rowstart[n];
        const int end = g_rowstart[n + 1];
        float4 acc = make_float4(0.f, 0.f, 0.f, 0.f);
        for (int j = beg + half; j < end; j += 2) {
            int s = __ldg(&g_csrc[j]);
            float4 v = *(const float4*)&g_u[s * D + cl];
            acc.x += v.x; acc.y += v.y; acc.z += v.z; acc.w += v.w;
        }
        acc.x += __shfl_xor_sync(0xffffffffu, acc.x, 16);
        acc.y += __shfl_xor_sync(0xffffffffu, acc.y, 16);
        acc.z += __shfl_xor_sync(0xffffffffu, acc.z, 16);
        acc.w += __shfl_xor_sync(0xffffffffu, acc.w, 16);
        if (half == 0) {
            float4 us = *(const float4*)&g_u[n * D + cl];
            float dv = g_dinv[n];
            float4 y;
            y.x = dv * (acc.x + us.x) + bv.x;
            y.y = dv * (acc.y + us.y) + bv.y;
            y.z = dv * (acc.z + us.z) + bv.z;
            y.w = dv * (acc.w + us.w) + bv.w;
            *(float4*)&g_y[n * D + cl] = y;
            s1x += y.x; s1y += y.y; s1z += y.z; s1w += y.w;
            s2x += y.x * y.x; s2y += y.y * y.y; s2z += y.z * y.z; s2w += y.w * y.w;
        }
    }

    if (half == 0) {
        sm1[w * 64 + cl + 0] = s1x; sm1[w * 64 + cl + 1] = s1y;
        sm1[w * 64 + cl + 2] = s1z; sm1[w * 64 + cl + 3] = s1w;
        sm2[w * 64 + cl + 0] = s2x; sm2[w * 64 + cl + 1] = s2y;
        sm2[w * 64 + cl + 2] = s2z; sm2[w * 64 + cl + 3] = s2w;
    }
    __syncthreads();
    if (tid < 64) {
        float t1 = 0.f, t2 = 0.f;
        #pragma unroll
        for (int ww = 0; ww < 8; ww++) { t1 += sm1[ww * 64 + tid]; t2 += sm2[ww * 64 + tid]; }
        atomicAdd(&g_stats[tid], t1);
        atomicAdd(&g_stats[D + tid], t2);
    }
    __threadfence();
    if (tid == 0) isLast = (atomicAdd(&g_cnt, 1u) == (unsigned)(gridDim.x - 1));
    __syncthreads();
    if (isLast) {
        if (tid < 64) {
            float mean = g_stats[tid] * (1.0f / N_NODES);
            float var  = g_stats[D + tid] * (1.0f / N_NODES) - mean * mean;
            float sc = gamma[tid] * rsqrtf(var + BN_EPS);
            g_scale[tid] = sc;
            g_shift[tid] = beta[tid] - mean * sc;
        }
        if (tid == 0) g_cnt = 0u;   // rearm
    }
}

// final layer: h = relu(y*scale+shift); pooled[batch[n]] += h  (fused)
__global__ void k_poolfused(const int* __restrict__ batch) {
    long long idx = (long long)blockIdx.x * blockDim.x + threadIdx.x;
    if (idx >= (long long)N_NODES * 16) return;
    int n = (int)(idx >> 4);
    int c = (int)(idx & 15) << 2;
    int g = __ldg(&batch[n]);
    float4 y  = *(const float4*)&g_y[n * D + c];
    float4 sc = *(const float4*)&g_scale[c];
    float4 sh = *(const float4*)&g_shift[c];
    float4 h;
    h.x = fmaxf(y.x * sc.x + sh.x, 0.0f);
    h.y = fmaxf(y.y * sc.y + sh.y, 0.0f);
    h.z = fmaxf(y.z * sc.z + sh.z, 0.0f);
    h.w = fmaxf(y.w * sc.w + sh.w, 0.0f);
    red_add_v4(&g_pooled[g * D + c], h);
}

// tiny MLP head: one block per graph, 64 threads
__global__ void k_mlp(const float* __restrict__ w1, const float* __restrict__ b1,
                      const float* __restrict__ w2, const float* __restrict__ b2,
                      const float* __restrict__ w3, const float* __restrict__ b3,
                      float* __restrict__ out) {
    __shared__ float pr[64], z1[64], z2[64], red[64];
    const int g = blockIdx.x;
    const int c = threadIdx.x;
    pr[c] = g_pooled[g * D + c];
    __syncthreads();
    float a = b1[c];
    #pragma unroll 8
    for (int k = 0; k < 64; k++) a += pr[k] * w1[k * D + c];
    z1[c] = fmaxf(a, 0.0f);
    __syncthreads();
    a = b2[c];
    #pragma unroll 8
    for (int k = 0; k < 64; k++) a += z1[k] * w2[k * D + c];
    z2[c] = fmaxf(a, 0.0f);
    __syncthreads();
    red[c] = z2[c] * w3[c];
    __syncthreads();
    if (c == 0) {
        float s = b3[0];
        #pragma unroll
        for (int k = 0; k < 64; k++) s += red[k];
        out[g] = s;
    }
}

// ---------------- launch -----------------------------------------------------
extern "C" void kernel_launch(void* const* d_in, const int* in_sizes, int n_in,
                              void* d_out, int out_size) {
    const float* x     = (const float*)d_in[0];
    const int*   ei    = (const int*)d_in[1];
    const int*   batch = (const int*)d_in[2];
    const float* Ws    = (const float*)d_in[3];
    const float* bs    = (const float*)d_in[4];
    const float* gamma = (const float*)d_in[5];
    const float* beta  = (const float*)d_in[6];
    const float* w1    = (const float*)d_in[7];
    const float* b1    = (const float*)d_in[8];
    const float* w2    = (const float*)d_in[9];
    const float* b2    = (const float*)d_in[10];
    const float* w3    = (const float*)d_in[11];
    const float* b3    = (const float*)d_in[12];
    float* out = (float*)d_out;

    // CSR build (once per launch)
    k_init<<<(N_GRAPHS * D + 255) / 256, 256>>>();
    k_count<<<(N_EDGES + 255) / 256, 256>>>(ei);
    k_scan1<<<SCAN_NBLK, SCAN_BLK>>>();
    k_scan2<<<1, 128>>>();
    k_scan3<<<(N_NODES + 255) / 256, 256>>>();
    k_fill<<<(N_EDGES + 255) / 256, 256>>>(ei);

    for (int l = 0; l < N_LAYERS; l++) {
        const float* hin = (l == 0) ? x : nullptr;  // nullptr => fused BN+ReLU from g_y
        k_gemm<<<GEMM_NT, 256>>>(hin, Ws + l * D * D);
        k_gather<<<GATHER_GRID, 256>>>(bs + l * D, gamma + l * D, beta + l * D);
    }

    k_poolfused<<<(N_NODES * 16) / 256, 256>>>(batch);
    k_mlp<<<N_GRAPHS, 64>>>(w1, b1, w2, b2, w3, b3, out);
}

// round 11
// speedup vs baseline: 1.1359x; 1.1111x over previous
#include <cuda_runtime.h>
#include <cuda_bf16.h>
#include <cstdint>

#define N_NODES 50000
#define N_EDGES 800000
#define D 64
#define N_GRAPHS 1024
#define N_LAYERS 4
#define BN_EPS 1e-5f

#define SCAN_BLK 512
#define SCAN_NBLK ((N_NODES + SCAN_BLK - 1) / SCAN_BLK)   // 98
#define GATHER_GRID 1184                                  // 148*8 blocks
#define GEMM_NT ((N_NODES + 63) / 64)                     // 782 row tiles
#define GEMM_GRID 296                                     // persistent: 148 SM * 2
#define HPAD 68                                           // smem row pad (16B-aligned)

// ---------------- scratch (device globals; no allocations allowed) ----------
__device__ __align__(16) float g_u[N_NODES * D];      // (h@W)*dinv[row]
__device__ __align__(16) float g_y[N_NODES * D];      // pre-BN activations
__device__ __align__(16) float g_dinv[N_NODES];       // rsqrt(deg)
__device__ __align__(16) float g_pooled[N_GRAPHS * D];
__device__ __align__(16) float g_stats[2 * D];        // [sum, sumsq]
__device__ __align__(16) float g_scale[D];
__device__ __align__(16) float g_shift[D];
__device__ int   g_count[N_NODES];                    // in-degree histogram
__device__ int   g_rowtmp[N_NODES];                   // local exclusive scan
__device__ int   g_rowstart[N_NODES + 1];             // CSR row offsets
__device__ int   g_cursor[N_NODES];                   // fill cursors
__device__ int   g_csrc[N_EDGES];                     // CSR src lists (by dst)
__device__ int   g_bsum[SCAN_NBLK + 2];               // scan block sums
__device__ unsigned int g_cnt;                         // last-block ticket

// vectorized global reduction (fp32 add, no return) — sm_90+
__device__ __forceinline__ void red_add_v4(float* addr, float4 v) {
    asm volatile("red.global.add.v4.f32 [%0], {%1,%2,%3,%4};"
                 :: "l"(addr), "f"(v.x), "f"(v.y), "f"(v.z), "f"(v.w)
                 : "memory");
}

// fp32 -> tf32 (round-to-nearest)
__device__ __forceinline__ uint32_t f2tf32(float x) {
    uint32_t r;
    asm("cvt.rna.tf32.f32 %0, %1;" : "=r"(r) : "f"(x));
    return r;
}

__device__ __forceinline__ void mma_tf32(float& d0, float& d1, float& d2, float& d3,
                                         uint32_t a0, uint32_t a1, uint32_t a2, uint32_t a3,
                                         uint32_t b0, uint32_t b1) {
    asm volatile(
        "mma.sync.aligned.m16n8k8.row.col.f32.tf32.tf32.f32 "
        "{%0,%1,%2,%3}, {%4,%5,%6,%7}, {%8,%9}, {%0,%1,%2,%3};"
        : "+f"(d0), "+f"(d1), "+f"(d2), "+f"(d3)
        : "r"(a0), "r"(a1), "r"(a2), "r"(a3), "r"(b0), "r"(b1));
}

// ---------------- setup kernels ---------------------------------------------

__global__ void k_init() {
    int i = blockIdx.x * blockDim.x + threadIdx.x;
    if (i < N_NODES) g_count[i] = 0;
    if (i < N_GRAPHS * D) g_pooled[i] = 0.0f;
    if (i == 0) g_cnt = 0u;
}

__global__ void k_count(const int* __restrict__ ei) {
    int e = blockIdx.x * blockDim.x + threadIdx.x;
    if (e < N_EDGES) atomicAdd(&g_count[ei[N_EDGES + e]], 1);
}

__global__ void k_scan1() {
    __shared__ int sm[SCAN_BLK];
    int i = blockIdx.x * SCAN_BLK + threadIdx.x;
    int v = (i < N_NODES) ? g_count[i] : 0;
    sm[threadIdx.x] = v;
    __syncthreads();
    for (int off = 1; off < SCAN_BLK; off <<= 1) {
        int t = (threadIdx.x >= off) ? sm[threadIdx.x - off] : 0;
        __syncthreads();
        sm[threadIdx.x] += t;
        __syncthreads();
    }
    if (i < N_NODES) g_rowtmp[i] = sm[threadIdx.x] - v;  // exclusive
    if (threadIdx.x == SCAN_BLK - 1) g_bsum[blockIdx.x] = sm[SCAN_BLK - 1];
}

__global__ void k_scan2() {
    __shared__ int sm[128];
    int t = threadIdx.x;
    int v = (t < SCAN_NBLK) ? g_bsum[t] : 0;
    sm[t] = v;
    __syncthreads();
    #pragma unroll
    for (int off = 1; off < 128; off <<= 1) {
        int u = (t >= off) ? sm[t - off] : 0;
        __syncthreads();
        sm[t] += u;
        __syncthreads();
    }
    if (t < SCAN_NBLK) g_bsum[t] = sm[t] - v;  // exclusive
}

__global__ void k_scan3() {
    int i = blockIdx.x * blockDim.x + threadIdx.x;
    if (i < N_NODES) {
        int rs = g_rowtmp[i] + g_bsum[i >> 9];
        g_rowstart[i] = rs;
        g_cursor[i]   = rs;
        g_dinv[i] = rsqrtf((float)g_count[i] + 1.0f);
    }
    if (i == 0) g_rowstart[N_NODES] = N_EDGES;
}

__global__ void k_fill(const int* __restrict__ ei) {
    int e = blockIdx.x * blockDim.x + threadIdx.x;
    if (e < N_EDGES) {
        int s = ei[e];
        int d = ei[N_EDGES + e];
        int pos = atomicAdd(&g_cursor[d], 1);
        g_csrc[pos] = s;
    }
}

// ---------------- per-layer kernels ------------------------------------------

// Persistent tensor-core GEMM via C^T = W^T x H^T with 3xTF32 splitting.
// u[r][c] = (sum_k h[r][k]*W[k][c]) * dinv[r];
// hin == nullptr => h = relu(g_y * g_scale + g_shift) (fused BN+ReLU).
// W^T A-fragments extracted ONCE per block (register-stationary); H tiles are
// pre-split to tf32 hi/lo in smem at staging (cvt once per element, not per
// consuming warp); next tile's H prefetched into regs during compute.
__global__ void __launch_bounds__(256, 2) k_gemm(const float* __restrict__ hin_arg,
                                                 const float* __restrict__ W) {
    __shared__ __align__(16) uint32_t hhi[64 * HPAD];   // W staging first, then H-hi
    __shared__ __align__(16) uint32_t hlo[64 * HPAD];   // H-lo
    __shared__ float ssc[64], ssh[64], sdinv[64];

    const int tid  = threadIdx.x;
    const int lane = tid & 31;
    const int w    = tid >> 5;
    const int grp  = lane >> 2;     // 0..7
    const int tg   = lane & 3;      // 0..3
    const int cs   = (w & 3) * 16;  // c-strip base
    const int ng   = w >> 2;        // node half: 0/1

    if (blockIdx.x == 0 && tid < 2 * D) g_stats[tid] = 0.0f;  // pre-layer zero
    if (tid < 64) { ssc[tid] = g_scale[tid]; ssh[tid] = g_shift[tid]; }

    const bool bn = (hin_arg == nullptr);
    const float* src = bn ? (const float*)g_y : hin_arg;

    // staging-role indices (per thread: 4 rows x 4 consecutive k-cols)
    const int rr = tid >> 4;          // 0..15
    const int kk = (tid & 15) << 2;   // 0,4,..,60

    // prefetch tile0 H into registers (overlaps W staging below)
    float4 tmp4[4];
    int tile = blockIdx.x;
    {
        const int row0 = tile * 64;
        #pragma unroll
        for (int j = 0; j < 4; j++) {
            int gr = row0 + rr + j * 16;
            tmp4[j] = (gr < N_NODES) ? *(const float4*)&src[gr * D + kk]
                                     : make_float4(0.f, 0.f, 0.f, 0.f);
        }
    }

    // ---- stage W (row-major 64x64) into hhi region ----
    float* wst = (float*)hhi;
    for (int i = tid; i < 64 * 64; i += 256) wst[i] = W[i];
    __syncthreads();

    // ---- extract stationary A = W^T fragments (hi + lo), once per block ----
    uint32_t ahi[8][4], alo[8][4];
    #pragma unroll
    for (int s = 0; s < 8; s++) {
        float v[4];
        v[0] = wst[(8 * s + tg) * 64 + cs + grp];
        v[1] = wst[(8 * s + tg) * 64 + cs + grp + 8];
        v[2] = wst[(8 * s + tg + 4) * 64 + cs + grp];
        v[3] = wst[(8 * s + tg + 4) * 64 + cs + grp + 8];
        #pragma unroll
        for (int j = 0; j < 4; j++) {
            uint32_t h = f2tf32(v[j]);
            ahi[s][j] = h;
            alo[s][j] = f2tf32(v[j] - __uint_as_float(h));
        }
    }
    float4 sc4 = *(const float4*)&ssc[kk];
    float4 sh4 = *(const float4*)&ssh[kk];
    __syncthreads();   // done reading wst; hhi reusable

    for (; tile < GEMM_NT; tile += GEMM_GRID) {
        const int row0 = tile * 64;

        // ---- stage H tile: BN+ReLU, split to tf32 hi/lo, STS ----
        if (tid < 64) sdinv[tid] = (row0 + tid < N_NODES) ? g_dinv[row0 + tid] : 0.0f;
        #pragma unroll
        for (int j = 0; j < 4; j++) {
            float4 v = tmp4[j];
            if (bn) {
                v.x = fmaxf(v.x * sc4.x + sh4.x, 0.0f);
                v.y = fmaxf(v.y * sc4.y + sh4.y, 0.0f);
                v.z = fmaxf(v.z * sc4.z + sh4.z, 0.0f);
                v.w = fmaxf(v.w * sc4.w + sh4.w, 0.0f);
            }
            uint4 hi, lo;
            hi.x = f2tf32(v.x); lo.x = f2tf32(v.x - __uint_as_float(hi.x));
            hi.y = f2tf32(v.y); lo.y = f2tf32(v.y - __uint_as_float(hi.y));
            hi.z = f2tf32(v.z); lo.z = f2tf32(v.z - __uint_as_float(hi.z));
            hi.w = f2tf32(v.w); lo.w = f2tf32(v.w - __uint_as_float(hi.w));
            const int r = rr + j * 16;
            *(uint4*)&hhi[r * HPAD + kk] = hi;
            *(uint4*)&hlo[r * HPAD + kk] = lo;
        }
        __syncthreads();

        // ---- prefetch next tile's H (overlaps compute) ----
        const int next = tile + GEMM_GRID;
        if (next < GEMM_NT) {
            const int nrow0 = next * 64;
            #pragma unroll
            for (int j = 0; j < 4; j++) {
                int gr = nrow0 + rr + j * 16;
                tmp4[j] = (gr < N_NODES) ? *(const float4*)&src[gr * D + kk]
                                         : make_float4(0.f, 0.f, 0.f, 0.f);
            }
        }

        // ---- compute: warp covers c-strip [cs,cs+16), nodes [ng*32,+32) ----
        #pragma unroll
        for (int chunk = 0; chunk < 4; chunk++) {
            const int n0l = ng * 32 + chunk * 8;
            float d0 = 0.f, d1 = 0.f, d2 = 0.f, d3 = 0.f;
            #pragma unroll
            for (int s = 0; s < 8; s++) {
                const int bidx = (n0l + grp) * HPAD + 8 * s + tg;
                uint32_t bh0 = hhi[bidx], bh1 = hhi[bidx + 4];
                uint32_t bl0 = hlo[bidx], bl1 = hlo[bidx + 4];
                mma_tf32(d0, d1, d2, d3, ahi[s][0], ahi[s][1], ahi[s][2], ahi[s][3], bh0, bh1);
                mma_tf32(d0, d1, d2, d3, ahi[s][0], ahi[s][1], ahi[s][2], ahi[s][3], bl0, bl1);
                mma_tf32(d0, d1, d2, d3, alo[s][0], alo[s][1], alo[s][2], alo[s][3], bh0, bh1);
            }
            // C^T frag -> g_u: d0=C^T[grp][2tg], d1=[grp][2tg+1], d2=[grp+8][2tg], d3=[grp+8][2tg+1]
            const int nA = row0 + n0l + 2 * tg;
            const int nB = nA + 1;
            const float dvA = sdinv[n0l + 2 * tg];
            const float dvB = sdinv[n0l + 2 * tg + 1];
            const int cA = cs + grp, cB = cs + grp + 8;
            if (nA < N_NODES) { g_u[nA * D + cA] = d0 * dvA; g_u[nA * D + cB] = d2 * dvA; }
            if (nB < N_NODES) { g_u[nB * D + cA] = d1 * dvB; g_u[nB * D + cB] = d3 * dvB; }
        }
        __syncthreads();   // hhi/hlo/sdinv reads done before next staging
    }
}

// CSR gather + y + BN stats + ticket finalize.  One warp per node (grid-stride).
__global__ void __launch_bounds__(256) k_gather(const float* __restrict__ b,
                                                const float* __restrict__ gamma,
                                                const float* __restrict__ beta) {
    __shared__ float sm1[8 * 64];
    __shared__ float sm2[8 * 64];
    __shared__ bool isLast;

    const int tid = threadIdx.x;
    const int w = tid >> 5;
    const int lane = tid & 31;
    const int half = lane >> 4;
    const int cl = (lane & 15) << 2;

    float s1x = 0.f, s1y = 0.f, s1z = 0.f, s1w = 0.f;
    float s2x = 0.f, s2y = 0.f, s2z = 0.f, s2w = 0.f;
    const float4 bv = *(const float4*)&b[cl];

    for (int n = blockIdx.x * 8 + w; n < N_NODES; n += GATHER_GRID * 8) {
        const int beg = g_rowstart[n];
        const int end = g_rowstart[n + 1];
        float4 acc = make_float4(0.f, 0.f, 0.f, 0.f);
        for (int j = beg + half; j < end; j += 2) {
            int s = __ldg(&g_csrc[j]);
            float4 v = *(const float4*)&g_u[s * D + cl];
            acc.x += v.x; acc.y += v.y; acc.z += v.z; acc.w += v.w;
        }
        acc.x += __shfl_xor_sync(0xffffffffu, acc.x, 16);
        acc.y += __shfl_xor_sync(0xffffffffu, acc.y, 16);
        acc.z += __shfl_xor_sync(0xffffffffu, acc.z, 16);
        acc.w += __shfl_xor_sync(0xffffffffu, acc.w, 16);
        if (half == 0) {
            float4 us = *(const float4*)&g_u[n * D + cl];
            float dv = g_dinv[n];
            float4 y;
            y.x = dv * (acc.x + us.x) + bv.x;
            y.y = dv * (acc.y + us.y) + bv.y;
            y.z = dv * (acc.z + us.z) + bv.z;
            y.w = dv * (acc.w + us.w) + bv.w;
            *(float4*)&g_y[n * D + cl] = y;
            s1x += y.x; s1y += y.y; s1z += y.z; s1w += y.w;
            s2x += y.x * y.x; s2y += y.y * y.y; s2z += y.z * y.z; s2w += y.w * y.w;
        }
    }

    if (half == 0) {
        sm1[w * 64 + cl + 0] = s1x; sm1[w * 64 + cl + 1] = s1y;
        sm1[w * 64 + cl + 2] = s1z; sm1[w * 64 + cl + 3] = s1w;
        sm2[w * 64 + cl + 0] = s2x; sm2[w * 64 + cl + 1] = s2y;
        sm2[w * 64 + cl + 2] = s2z; sm2[w * 64 + cl + 3] = s2w;
    }
    __syncthreads();
    if (tid < 64) {
        float t1 = 0.f, t2 = 0.f;
        #pragma unroll
        for (int ww = 0; ww < 8; ww++) { t1 += sm1[ww * 64 + tid]; t2 += sm2[ww * 64 + tid]; }
        atomicAdd(&g_stats[tid], t1);
        atomicAdd(&g_stats[D + tid], t2);
    }
    __threadfence();
    if (tid == 0) isLast = (atomicAdd(&g_cnt, 1u) == (unsigned)(gridDim.x - 1));
    __syncthreads();
    if (isLast) {
        if (tid < 64) {
            float mean = g_stats[tid] * (1.0f / N_NODES);
            float var  = g_stats[D + tid] * (1.0f / N_NODES) - mean * mean;
            float sc = gamma[tid] * rsqrtf(var + BN_EPS);
            g_scale[tid] = sc;
            g_shift[tid] = beta[tid] - mean * sc;
        }
        if (tid == 0) g_cnt = 0u;   // rearm
    }
}

// final layer: h = relu(y*scale+shift); pooled[batch[n]] += h  (fused)
__global__ void k_poolfused(const int* __restrict__ batch) {
    long long idx = (long long)blockIdx.x * blockDim.x + threadIdx.x;
    if (idx >= (long long)N_NODES * 16) return;
    int n = (int)(idx >> 4);
    int c = (int)(idx & 15) << 2;
    int g = __ldg(&batch[n]);
    float4 y  = *(const float4*)&g_y[n * D + c];
    float4 sc = *(const float4*)&g_scale[c];
    float4 sh = *(const float4*)&g_shift[c];
    float4 h;
    h.x = fmaxf(y.x * sc.x + sh.x, 0.0f);
    h.y = fmaxf(y.y * sc.y + sh.y, 0.0f);
    h.z = fmaxf(y.z * sc.z + sh.z, 0.0f);
    h.w = fmaxf(y.w * sc.w + sh.w, 0.0f);
    red_add_v4(&g_pooled[g * D + c], h);
}

// tiny MLP head: one block per graph, 64 threads
__global__ void k_mlp(const float* __restrict__ w1, const float* __restrict__ b1,
                      const float* __restrict__ w2, const float* __restrict__ b2,
                      const float* __restrict__ w3, const float* __restrict__ b3,
                      float* __restrict__ out) {
    __shared__ float pr[64], z1[64], z2[64], red[64];
    const int g = blockIdx.x;
    const int c = threadIdx.x;
    pr[c] = g_pooled[g * D + c];
    __syncthreads();
    float a = b1[c];
    #pragma unroll 8
    for (int k = 0; k < 64; k++) a += pr[k] * w1[k * D + c];
    z1[c] = fmaxf(a, 0.0f);
    __syncthreads();
    a = b2[c];
    #pragma unroll 8
    for (int k = 0; k < 64; k++) a += z1[k] * w2[k * D + c];
    z2[c] = fmaxf(a, 0.0f);
    __syncthreads();
    red[c] = z2[c] * w3[c];
    __syncthreads();
    if (c == 0) {
        float s = b3[0];
        #pragma unroll
        for (int k = 0; k < 64; k++) s += red[k];
        out[g] = s;
    }
}

// ---------------- launch -----------------------------------------------------
extern "C" void kernel_launch(void* const* d_in, const int* in_sizes, int n_in,
                              void* d_out, int out_size) {
    const float* x     = (const float*)d_in[0];
    const int*   ei    = (const int*)d_in[1];
    const int*   batch = (const int*)d_in[2];
    const float* Ws    = (const float*)d_in[3];
    const float* bs    = (const float*)d_in[4];
    const float* gamma = (const float*)d_in[5];
    const float* beta  = (const float*)d_in[6];
    const float* w1    = (const float*)d_in[7];
    const float* b1    = (const float*)d_in[8];
    const float* w2    = (const float*)d_in[9];
    const float* b2    = (const float*)d_in[10];
    const float* w3    = (const float*)d_in[11];
    const float* b3    = (const float*)d_in[12];
    float* out = (float*)d_out;

    // CSR build (once per launch)
    k_init<<<(N_GRAPHS * D + 255) / 256, 256>>>();
    k_count<<<(N_EDGES + 255) / 256, 256>>>(ei);
    k_scan1<<<SCAN_NBLK, SCAN_BLK>>>();
    k_scan2<<<1, 128>>>();
    k_scan3<<<(N_NODES + 255) / 256, 256>>>();
    k_fill<<<(N_EDGES + 255) / 256, 256>>>(ei);

    for (int l = 0; l < N_LAYERS; l++) {
        const float* hin = (l == 0) ? x : nullptr;  // nullptr => fused BN+ReLU from g_y
        k_gemm<<<GEMM_GRID, 256>>>(hin, Ws + l * D * D);
        k_gather<<<GATHER_GRID, 256>>>(bs + l * D, gamma + l * D, beta + l * D);
    }

    k_poolfused<<<(N_NODES * 16) / 256, 256>>>(batch);
    k_mlp<<<N_GRAPHS, 64>>>(w1, b1, w2, b2, w3, b3, out);
}

// round 12
// speedup vs baseline: 1.1567x; 1.0183x over previous
#include <cuda_runtime.h>
#include <cuda_bf16.h>
#include <cuda_fp16.h>
#include <cstdint>

#define N_NODES 50000
#define N_EDGES 800000
#define D 64
#define N_GRAPHS 1024
#define N_LAYERS 4
#define BN_EPS 1e-5f

#define SCAN_BLK 512
#define SCAN_NBLK ((N_NODES + SCAN_BLK - 1) / SCAN_BLK)   // 98
#define GATHER_GRID 1184                                  // 148*8 blocks
#define GEMM_NT ((N_NODES + 63) / 64)                     // 782 row tiles
#define GEMM_GRID 296                                     // persistent: 148 SM * 2
#define HPAD 68                                           // smem row pad (16B-aligned)

// ---------------- scratch (device globals; no allocations allowed) ----------
__device__ __align__(16) __half g_u16[N_NODES * D];   // fp16 u = (h@W)*dinv  (gather payload)
__device__ __align__(16) float g_y[N_NODES * D];      // pre-BN activations
__device__ __align__(16) float g_dinv[N_NODES];       // rsqrt(deg)
__device__ __align__(16) float g_pooled[N_GRAPHS * D];
__device__ __align__(16) float g_stats[2 * D];        // [sum, sumsq]
__device__ __align__(16) float g_scale[D];
__device__ __align__(16) float g_shift[D];
__device__ int   g_count[N_NODES];                    // in-degree histogram
__device__ int   g_rowstart[N_NODES];                 // CSR row begin (arrival-order base)
__device__ int   g_rowend[N_NODES];                   // CSR row end
__device__ int   g_cursor[N_NODES];                   // fill cursors
__device__ int   g_csrc[N_EDGES];                     // CSR src lists (by dst)
__device__ int   g_total;                              // global range cursor
__device__ unsigned int g_cnt;                         // last-block ticket

// vectorized global reduction (fp32 add, no return) — sm_90+
__device__ __forceinline__ void red_add_v4(float* addr, float4 v) {
    asm volatile("red.global.add.v4.f32 [%0], {%1,%2,%3,%4};"
                 :: "l"(addr), "f"(v.x), "f"(v.y), "f"(v.z), "f"(v.w)
                 : "memory");
}

// fp32 -> tf32 (round-to-nearest)
__device__ __forceinline__ uint32_t f2tf32(float x) {
    uint32_t r;
    asm("cvt.rna.tf32.f32 %0, %1;" : "=r"(r) : "f"(x));
    return r;
}

__device__ __forceinline__ void mma_tf32(float& d0, float& d1, float& d2, float& d3,
                                         uint32_t a0, uint32_t a1, uint32_t a2, uint32_t a3,
                                         uint32_t b0, uint32_t b1) {
    asm volatile(
        "mma.sync.aligned.m16n8k8.row.col.f32.tf32.tf32.f32 "
        "{%0,%1,%2,%3}, {%4,%5,%6,%7}, {%8,%9}, {%0,%1,%2,%3};"
        : "+f"(d0), "+f"(d1), "+f"(d2), "+f"(d3)
        : "r"(a0), "r"(a1), "r"(a2), "r"(a3), "r"(b0), "r"(b1));
}

// ---------------- setup kernels ---------------------------------------------

__global__ void k_init() {
    int i = blockIdx.x * blockDim.x + threadIdx.x;
    if (i < N_NODES) g_count[i] = 0;
    if (i < N_GRAPHS * D) g_pooled[i] = 0.0f;
    if (i == 0) { g_cnt = 0u; g_total = 0; }
}

__global__ void k_count(const int* __restrict__ ei) {
    int e = blockIdx.x * blockDim.x + threadIdx.x;
    if (e < N_EDGES) atomicAdd(&g_count[ei[N_EDGES + e]], 1);
}

// single-kernel range assignment: block scan + one atomicAdd for base.
// CSR ranges are contiguous per node; global placement is arrival-order
// (output-equivalent: per-node edge sets unchanged). Also computes dinv.
__global__ void k_scanA() {
    __shared__ int sm[SCAN_BLK];
    __shared__ int base;
    int tid = threadIdx.x;
    int i = blockIdx.x * SCAN_BLK + tid;
    int v = (i < N_NODES) ? g_count[i] : 0;
    sm[tid] = v;
    __syncthreads();
    for (int off = 1; off < SCAN_BLK; off <<= 1) {
        int t = (tid >= off) ? sm[tid - off] : 0;
        __syncthreads();
        sm[tid] += t;
        __syncthreads();
    }
    if (tid == SCAN_BLK - 1) base = atomicAdd(&g_total, sm[SCAN_BLK - 1]);
    __syncthreads();
    if (i < N_NODES) {
        int rs = base + sm[tid] - v;   // exclusive within block + block base
        g_rowstart[i] = rs;
        g_rowend[i]   = rs + v;
        g_cursor[i]   = rs;
        g_dinv[i] = rsqrtf((float)v + 1.0f);
    }
}

__global__ void k_fill(const int* __restrict__ ei) {
    int e = blockIdx.x * blockDim.x + threadIdx.x;
    if (e < N_EDGES) {
        int s = ei[e];
        int d = ei[N_EDGES + e];
        int pos = atomicAdd(&g_cursor[d], 1);
        g_csrc[pos] = s;
    }
}

// ---------------- per-layer kernels ------------------------------------------

// Persistent tensor-core GEMM via C^T = W^T x H^T with 3xTF32 splitting.
// u16[r][c] = fp16( (sum_k h[r][k]*W[k][c]) * dinv[r] );
// hin == nullptr => h = relu(g_y * g_scale + g_shift) (fused BN+ReLU).
__global__ void __launch_bounds__(256, 2) k_gemm(const float* __restrict__ hin_arg,
                                                 const float* __restrict__ W) {
    __shared__ __align__(16) uint32_t hhi[64 * HPAD];   // W staging first, then H-hi
    __shared__ __align__(16) uint32_t hlo[64 * HPAD];   // H-lo
    __shared__ float ssc[64], ssh[64], sdinv[64];

    const int tid  = threadIdx.x;
    const int lane = tid & 31;
    const int w    = tid >> 5;
    const int grp  = lane >> 2;     // 0..7
    const int tg   = lane & 3;      // 0..3
    const int cs   = (w & 3) * 16;  // c-strip base
    const int ng   = w >> 2;        // node half: 0/1

    if (blockIdx.x == 0 && tid < 2 * D) g_stats[tid] = 0.0f;  // pre-layer zero
    if (tid < 64) { ssc[tid] = g_scale[tid]; ssh[tid] = g_shift[tid]; }

    const bool bn = (hin_arg == nullptr);
    const float* src = bn ? (const float*)g_y : hin_arg;

    const int rr = tid >> 4;          // 0..15
    const int kk = (tid & 15) << 2;   // 0,4,..,60

    // prefetch tile0 H into registers
    float4 tmp4[4];
    int tile = blockIdx.x;
    {
        const int row0 = tile * 64;
        #pragma unroll
        for (int j = 0; j < 4; j++) {
            int gr = row0 + rr + j * 16;
            tmp4[j] = (gr < N_NODES) ? *(const float4*)&src[gr * D + kk]
                                     : make_float4(0.f, 0.f, 0.f, 0.f);
        }
    }

    // ---- stage W (row-major 64x64) into hhi region ----
    float* wst = (float*)hhi;
    for (int i = tid; i < 64 * 64; i += 256) wst[i] = W[i];
    __syncthreads();

    // ---- extract stationary A = W^T fragments (hi + lo), once per block ----
    uint32_t ahi[8][4], alo[8][4];
    #pragma unroll
    for (int s = 0; s < 8; s++) {
        float v[4];
        v[0] = wst[(8 * s + tg) * 64 + cs + grp];
        v[1] = wst[(8 * s + tg) * 64 + cs + grp + 8];
        v[2] = wst[(8 * s + tg + 4) * 64 + cs + grp];
        v[3] = wst[(8 * s + tg + 4) * 64 + cs + grp + 8];
        #pragma unroll
        for (int j = 0; j < 4; j++) {
            uint32_t h = f2tf32(v[j]);
            ahi[s][j] = h;
            alo[s][j] = f2tf32(v[j] - __uint_as_float(h));
        }
    }
    float4 sc4 = *(const float4*)&ssc[kk];
    float4 sh4 = *(const float4*)&ssh[kk];
    __syncthreads();   // done reading wst; hhi reusable

    for (; tile < GEMM_NT; tile += GEMM_GRID) {
        const int row0 = tile * 64;

        // ---- stage H tile: BN+ReLU, split to tf32 hi/lo, STS ----
        if (tid < 64) sdinv[tid] = (row0 + tid < N_NODES) ? g_dinv[row0 + tid] : 0.0f;
        #pragma unroll
        for (int j = 0; j < 4; j++) {
            float4 v = tmp4[j];
            if (bn) {
                v.x = fmaxf(v.x * sc4.x + sh4.x, 0.0f);
                v.y = fmaxf(v.y * sc4.y + sh4.y, 0.0f);
                v.z = fmaxf(v.z * sc4.z + sh4.z, 0.0f);
                v.w = fmaxf(v.w * sc4.w + sh4.w, 0.0f);
            }
            uint4 hi, lo;
            hi.x = f2tf32(v.x); lo.x = f2tf32(v.x - __uint_as_float(hi.x));
            hi.y = f2tf32(v.y); lo.y = f2tf32(v.y - __uint_as_float(hi.y));
            hi.z = f2tf32(v.z); lo.z = f2tf32(v.z - __uint_as_float(hi.z));
            hi.w = f2tf32(v.w); lo.w = f2tf32(v.w - __uint_as_float(hi.w));
            const int r = rr + j * 16;
            *(uint4*)&hhi[r * HPAD + kk] = hi;
            *(uint4*)&hlo[r * HPAD + kk] = lo;
        }
        __syncthreads();

        // ---- prefetch next tile's H (overlaps compute) ----
        const int next = tile + GEMM_GRID;
        if (next < GEMM_NT) {
            const int nrow0 = next * 64;
            #pragma unroll
            for (int j = 0; j < 4; j++) {
                int gr = nrow0 + rr + j * 16;
                tmp4[j] = (gr < N_NODES) ? *(const float4*)&src[gr * D + kk]
                                         : make_float4(0.f, 0.f, 0.f, 0.f);
            }
        }

        // ---- compute: warp covers c-strip [cs,cs+16), nodes [ng*32,+32) ----
        #pragma unroll
        for (int chunk = 0; chunk < 4; chunk++) {
            const int n0l = ng * 32 + chunk * 8;
            float d0 = 0.f, d1 = 0.f, d2 = 0.f, d3 = 0.f;
            #pragma unroll
            for (int s = 0; s < 8; s++) {
                const int bidx = (n0l + grp) * HPAD + 8 * s + tg;
                uint32_t bh0 = hhi[bidx], bh1 = hhi[bidx + 4];
                uint32_t bl0 = hlo[bidx], bl1 = hlo[bidx + 4];
                mma_tf32(d0, d1, d2, d3, ahi[s][0], ahi[s][1], ahi[s][2], ahi[s][3], bh0, bh1);
                mma_tf32(d0, d1, d2, d3, ahi[s][0], ahi[s][1], ahi[s][2], ahi[s][3], bl0, bl1);
                mma_tf32(d0, d1, d2, d3, alo[s][0], alo[s][1], alo[s][2], alo[s][3], bh0, bh1);
            }
            // C^T frag -> g_u16 (fp16): d0=C^T[grp][2tg], d1=[grp][2tg+1], d2=[grp+8][2tg], d3=[grp+8][2tg+1]
            const int nA = row0 + n0l + 2 * tg;
            const int nB = nA + 1;
            const float dvA = sdinv[n0l + 2 * tg];
            const float dvB = sdinv[n0l + 2 * tg + 1];
            const int cA = cs + grp, cB = cs + grp + 8;
            if (nA < N_NODES) {
                g_u16[nA * D + cA] = __float2half(d0 * dvA);
                g_u16[nA * D + cB] = __float2half(d2 * dvA);
            }
            if (nB < N_NODES) {
                g_u16[nB * D + cA] = __float2half(d1 * dvB);
                g_u16[nB * D + cB] = __float2half(d3 * dvB);
            }
        }
        __syncthreads();   // hhi/hlo/sdinv reads done before next staging
    }
}

// CSR gather (fp16 u) + y + BN stats + ticket finalize. One warp per node.
// Half-warps alternate edges; 16 lanes cover 64 cols as 4 halves (8B) each.
__global__ void __launch_bounds__(256) k_gather(const float* __restrict__ b,
                                                const float* __restrict__ gamma,
                                                const float* __restrict__ beta) {
    __shared__ float sm1[8 * 64];
    __shared__ float sm2[8 * 64];
    __shared__ bool isLast;

    const int tid = threadIdx.x;
    const int w = tid >> 5;
    const int lane = tid & 31;
    const int half = lane >> 4;
    const int cl = (lane & 15) << 2;   // column base (4 cols per lane)

    float s1x = 0.f, s1y = 0.f, s1z = 0.f, s1w = 0.f;
    float s2x = 0.f, s2y = 0.f, s2z = 0.f, s2w = 0.f;
    const float4 bv = *(const float4*)&b[cl];

    for (int n = blockIdx.x * 8 + w; n < N_NODES; n += GATHER_GRID * 8) {
        const int beg = g_rowstart[n];
        const int end = g_rowend[n];
        float4 acc = make_float4(0.f, 0.f, 0.f, 0.f);
        for (int j = beg + half; j < end; j += 2) {
            int s = __ldg(&g_csrc[j]);
            uint2 raw = *(const uint2*)&g_u16[s * D + cl];
            float2 f0 = __half22float2(*(const __half2*)&raw.x);
            float2 f1 = __half22float2(*(const __half2*)&raw.y);
            acc.x += f0.x; acc.y += f0.y; acc.z += f1.x; acc.w += f1.y;
        }
        acc.x += __shfl_xor_sync(0xffffffffu, acc.x, 16);
        acc.y += __shfl_xor_sync(0xffffffffu, acc.y, 16);
        acc.z += __shfl_xor_sync(0xffffffffu, acc.z, 16);
        acc.w += __shfl_xor_sync(0xffffffffu, acc.w, 16);
        if (half == 0) {
            uint2 raws = *(const uint2*)&g_u16[n * D + cl];
            float2 u0 = __half22float2(*(const __half2*)&raws.x);
            float2 u1 = __half22float2(*(const __half2*)&raws.y);
            float dv = g_dinv[n];
            float4 y;
            y.x = dv * (acc.x + u0.x) + bv.x;
            y.y = dv * (acc.y + u0.y) + bv.y;
            y.z = dv * (acc.z + u1.x) + bv.z;
            y.w = dv * (acc.w + u1.y) + bv.w;
            *(float4*)&g_y[n * D + cl] = y;
            s1x += y.x; s1y += y.y; s1z += y.z; s1w += y.w;
            s2x += y.x * y.x; s2y += y.y * y.y; s2z += y.z * y.z; s2w += y.w * y.w;
        }
    }

    if (half == 0) {
        sm1[w * 64 + cl + 0] = s1x; sm1[w * 64 + cl + 1] = s1y;
        sm1[w * 64 + cl + 2] = s1z; sm1[w * 64 + cl + 3] = s1w;
        sm2[w * 64 + cl + 0] = s2x; sm2[w * 64 + cl + 1] = s2y;
        sm2[w * 64 + cl + 2] = s2z; sm2[w * 64 + cl + 3] = s2w;
    }
    __syncthreads();
    if (tid < 64) {
        float t1 = 0.f, t2 = 0.f;
        #pragma unroll
        for (int ww = 0; ww < 8; ww++) { t1 += sm1[ww * 64 + tid]; t2 += sm2[ww * 64 + tid]; }
        atomicAdd(&g_stats[tid], t1);
        atomicAdd(&g_stats[D + tid], t2);
    }
    __threadfence();
    if (tid == 0) isLast = (atomicAdd(&g_cnt, 1u) == (unsigned)(gridDim.x - 1));
    __syncthreads();
    if (isLast) {
        if (tid < 64) {
            float mean = g_stats[tid] * (1.0f / N_NODES);
            float var  = g_stats[D + tid] * (1.0f / N_NODES) - mean * mean;
            float sc = gamma[tid] * rsqrtf(var + BN_EPS);
            g_scale[tid] = sc;
            g_shift[tid] = beta[tid] - mean * sc;
        }
        if (tid == 0) g_cnt = 0u;   // rearm
    }
}

// final layer: h = relu(y*scale+shift); pooled[batch[n]] += h  (fused)
__global__ void k_poolfused(const int* __restrict__ batch) {
    long long idx = (long long)blockIdx.x * blockDim.x + threadIdx.x;
    if (idx >= (long long)N_NODES * 16) return;
    int n = (int)(idx >> 4);
    int c = (int)(idx & 15) << 2;
    int g = __ldg(&batch[n]);
    float4 y  = *(const float4*)&g_y[n * D + c];
    float4 sc = *(const float4*)&g_scale[c];
    float4 sh = *(const float4*)&g_shift[c];
    float4 h;
    h.x = fmaxf(y.x * sc.x + sh.x, 0.0f);
    h.y = fmaxf(y.y * sc.y + sh.y, 0.0f);
    h.z = fmaxf(y.z * sc.z + sh.z, 0.0f);
    h.w = fmaxf(y.w * sc.w + sh.w, 0.0f);
    red_add_v4(&g_pooled[g * D + c], h);
}

// tiny MLP head: one block per graph, 64 threads
__global__ void k_mlp(const float* __restrict__ w1, const float* __restrict__ b1,
                      const float* __restrict__ w2, const float* __restrict__ b2,
                      const float* __restrict__ w3, const float* __restrict__ b3,
                      float* __restrict__ out) {
    __shared__ float pr[64], z1[64], z2[64], red[64];
    const int g = blockIdx.x;
    const int c = threadIdx.x;
    pr[c] = g_pooled[g * D + c];
    __syncthreads();
    float a = b1[c];
    #pragma unroll 8
    for (int k = 0; k < 64; k++) a += pr[k] * w1[k * D + c];
    z1[c] = fmaxf(a, 0.0f);
    __syncthreads();
    a = b2[c];
    #pragma unroll 8
    for (int k = 0; k < 64; k++) a += z1[k] * w2[k * D + c];
    z2[c] = fmaxf(a, 0.0f);
    __syncthreads();
    red[c] = z2[c] * w3[c];
    __syncthreads();
    if (c == 0) {
        float s = b3[0];
        #pragma unroll
        for (int k = 0; k < 64; k++) s += red[k];
        out[g] = s;
    }
}

// ---------------- launch -----------------------------------------------------
extern "C" void kernel_launch(void* const* d_in, const int* in_sizes, int n_in,
                              void* d_out, int out_size) {
    const float* x     = (const float*)d_in[0];
    const int*   ei    = (const int*)d_in[1];
    const int*   batch = (const int*)d_in[2];
    const float* Ws    = (const float*)d_in[3];
    const float* bs    = (const float*)d_in[4];
    const float* gamma = (const float*)d_in[5];
    const float* beta  = (const float*)d_in[6];
    const float* w1    = (const float*)d_in[7];
    const float* b1    = (const float*)d_in[8];
    const float* w2    = (const float*)d_in[9];
    const float* b2    = (const float*)d_in[10];
    const float* w3    = (const float*)d_in[11];
    const float* b3    = (const float*)d_in[12];
    float* out = (float*)d_out;

    // CSR build (once per launch): init -> count -> range-assign -> fill
    k_init<<<(N_GRAPHS * D + 255) / 256, 256>>>();
    k_count<<<(N_EDGES + 255) / 256, 256>>>(ei);
    k_scanA<<<SCAN_NBLK, SCAN_BLK>>>();
    k_fill<<<(N_EDGES + 255) / 256, 256>>>(ei);

    for (int l = 0; l < N_LAYERS; l++) {
        const float* hin = (l == 0) ? x : nullptr;  // nullptr => fused BN+ReLU from g_y
        k_gemm<<<GEMM_GRID, 256>>>(hin, Ws + l * D * D);
        k_gather<<<GATHER_GRID, 256>>>(bs + l * D, gamma + l * D, beta + l * D);
    }

    k_poolfused<<<(N_NODES * 16) / 256, 256>>>(batch);
    k_mlp<<<N_GRAPHS, 64>>>(w1, b1, w2, b2, w3, b3, out);
}